// round 1
// baseline (speedup 1.0000x reference)
#include <cuda_runtime.h>
#include <cstdint>

// ---------------------------------------------------------------------------
// GroupVectorAttention — fp32 baseline with analytic BN1 folding + f32x2 GEMMs
// ---------------------------------------------------------------------------
// Shapes: B=4, N=4096, M=16, C=256, GROUPS=8, OUT_DIM=32
// Pipeline:
//   K1 diffstats   : sum(d), sum(d d^T) over all rows (deterministic 2-stage)
//   K2 fold        : fold BN1 into (256x3) weights for dm & db branches
//   K3 gemm q      : q = pf @ q_w^T + q_b                 (16384x256)
//   K4 gemm dm     : A-tile = relu(diff @ W1f_dm) on the fly, x dm_w2
//   K5 gemm db     : same with db weights
//   K6 gemm k      : nf @ k_w^T
//   K7 gemm v      : nf @ v_w^T
//   K8 attn        : va = dm*(q-k)+db ; grouped conv ; softmax(32) ; we = om*v
//                    + per-block channel sum/sumsq partials (deterministic)
//   K9 finalize2   : BN2 scale/shift
//   K10 gemm out   : A-tile = relu(we*s2+t2) on the fly, x lin_w  -> d_out
// ---------------------------------------------------------------------------

#define EPSV 1e-5f

static constexpr int Bb = 4, Nn = 4096, Mm = 16, Cd = 256;
static constexpr int R_ = Bb * Nn * Mm;       // 262144
static constexpr int BNp = Bb * Nn;           // 16384
static constexpr int STAT_BLOCKS = 256;
static constexpr int ATTN_BLOCKS = 512;       // 512 rows per block

typedef unsigned long long ull;

__device__ __forceinline__ ull pack2(float lo, float hi) {
    ull r; asm("mov.b64 %0, {%1, %2};" : "=l"(r) : "f"(lo), "f"(hi)); return r;
}
__device__ __forceinline__ ull dup2(float x) {
    ull r; asm("mov.b64 %0, {%1, %1};" : "=l"(r) : "f"(x)); return r;
}
__device__ __forceinline__ void ffma2(ull &d, ull a, ull b) {
    asm("fma.rn.f32x2 %0, %1, %2, %0;" : "+l"(d) : "l"(a), "l"(b));
}
__device__ __forceinline__ float2 unpk(ull v) {
    float2 f; asm("mov.b64 {%0, %1}, %2;" : "=f"(f.x), "=f"(f.y) : "l"(v)); return f;
}

// ------------------------- device scratch (static) -------------------------
__device__ float g_part1[STAT_BLOCKS * 12];
__device__ float g_w1f[2][Cd * 3];
__device__ float g_b1f[2][Cd];
__device__ float g_q[BNp * Cd];
__device__ float g_dm[(size_t)R_ * Cd];
__device__ float g_db[(size_t)R_ * Cd];
__device__ float g_k [(size_t)R_ * Cd];
__device__ float g_v [(size_t)R_ * Cd];
__device__ float g_we[(size_t)R_ * Cd];
__device__ float g_part2[ATTN_BLOCKS * 512];
__device__ float g_s2[Cd], g_t2[Cd];

// ------------------------------- K1: stats --------------------------------
__global__ void diffstats_kernel(const float* __restrict__ pts,
                                 const float* __restrict__ nbr) {
    float s[12];
#pragma unroll
    for (int i = 0; i < 12; i++) s[i] = 0.f;
    int tid = threadIdx.x;
    for (int r = blockIdx.x * blockDim.x + tid; r < R_; r += gridDim.x * blockDim.x) {
        int bn = r >> 4;
        float d[3];
#pragma unroll
        for (int j = 0; j < 3; j++) d[j] = pts[bn * 3 + j] - nbr[(size_t)r * 3 + j];
#pragma unroll
        for (int j = 0; j < 3; j++) s[j] += d[j];
#pragma unroll
        for (int j = 0; j < 3; j++)
#pragma unroll
            for (int k = 0; k < 3; k++) s[3 + j * 3 + k] += d[j] * d[k];
    }
    __shared__ float red[256];
    for (int comp = 0; comp < 12; comp++) {
        red[tid] = s[comp];
        __syncthreads();
        for (int off = 128; off > 0; off >>= 1) {
            if (tid < off) red[tid] += red[tid + off];
            __syncthreads();
        }
        if (tid == 0) g_part1[blockIdx.x * 12 + comp] = red[0];
        __syncthreads();
    }
}

// ------------------------------ K2: BN1 fold -------------------------------
__global__ void fold_kernel(const float* __restrict__ dm_w1, const float* __restrict__ dm_b1,
                            const float* __restrict__ dm_g,  const float* __restrict__ dm_be,
                            const float* __restrict__ db_w1, const float* __restrict__ db_b1,
                            const float* __restrict__ db_g,  const float* __restrict__ db_be) {
    __shared__ float st[12];
    __shared__ float mu[3], cov[9];
    int tid = threadIdx.x;
    if (tid < 12) {
        float a = 0.f;
        for (int b = 0; b < STAT_BLOCKS; b++) a += g_part1[b * 12 + tid];
        st[tid] = a / (float)R_;
    }
    __syncthreads();
    if (tid < 3) mu[tid] = st[tid];
    if (tid < 9) {
        int j = tid / 3, k = tid % 3;
        cov[tid] = st[3 + tid] - st[j] * st[k];
    }
    __syncthreads();
    int c = tid;
    for (int which = 0; which < 2; which++) {
        const float* w1 = which ? db_w1 : dm_w1;
        const float* b1 = which ? db_b1 : dm_b1;
        const float* gg = which ? db_g  : dm_g;
        const float* be = which ? db_be : dm_be;
        float w0 = w1[c * 3], w1v = w1[c * 3 + 1], w2v = w1[c * 3 + 2];
        float var = w0 * w0 * cov[0] + w1v * w1v * cov[4] + w2v * w2v * cov[8]
                  + 2.f * (w0 * w1v * cov[1] + w0 * w2v * cov[2] + w1v * w2v * cov[5]);
        float mdot = w0 * mu[0] + w1v * mu[1] + w2v * mu[2];
        float m = mdot + b1[c];
        float s = gg[c] * rsqrtf(var + EPSV);
        g_w1f[which][c * 3]     = w0 * s;
        g_w1f[which][c * 3 + 1] = w1v * s;
        g_w1f[which][c * 3 + 2] = w2v * s;
        g_b1f[which][c] = be[c] + s * (b1[c] - m);
    }
}

// ----------------------------- GEMM (f32x2) --------------------------------
// C_out[row, o] = sum_i Atile(row,i) * W[o, i] + bias[o]
// BM=128, BN=128 (grid.y=2 for 256 outs), BK=32, 256 threads, 8x8 microtile.
enum { AMODE_DIRECT = 0, AMODE_POS = 1, AMODE_BNRELU = 2 };

template <int AMODE>
__global__ void __launch_bounds__(256, 2)
gemm_kernel(const float* __restrict__ A, const float* __restrict__ W,
            const float* __restrict__ bias, float* __restrict__ Out,
            const float* __restrict__ pts, const float* __restrict__ nbr,
            int which) {
    __shared__ float As[32][128];
    __shared__ float Bs[32][128];
    int tid = threadIdx.x;
    int tx = tid & 15, ty = tid >> 4;
    int rowBase = blockIdx.x * 128;
    int nOff = blockIdx.y * 128;

    ull acc[8][4];
#pragma unroll
    for (int i = 0; i < 8; i++)
#pragma unroll
        for (int j = 0; j < 4; j++) acc[i][j] = 0ull;

    const float* w1f = g_w1f[which];
    const float* b1f = g_b1f[which];

    for (int kb = 0; kb < 256; kb += 32) {
#pragma unroll
        for (int i = 0; i < 4; i++) {
            int f = tid + i * 256;        // 0..1023
            int row = f >> 3, kq = f & 7; // 8 float4 per row of 32 k
            float4 av;
            if (AMODE == AMODE_DIRECT) {
                av = *(const float4*)&A[(size_t)(rowBase + row) * 256 + kb + kq * 4];
            } else if (AMODE == AMODE_POS) {
                int r = rowBase + row, bn = r >> 4;
                float d0 = pts[bn * 3]     - nbr[(size_t)r * 3];
                float d1 = pts[bn * 3 + 1] - nbr[(size_t)r * 3 + 1];
                float d2 = pts[bn * 3 + 2] - nbr[(size_t)r * 3 + 2];
                int k0 = kb + kq * 4;
                float tmp[4];
#pragma unroll
                for (int t = 0; t < 4; t++) {
                    float h = fmaf(d0, w1f[(k0 + t) * 3],
                              fmaf(d1, w1f[(k0 + t) * 3 + 1],
                              fmaf(d2, w1f[(k0 + t) * 3 + 2], b1f[k0 + t])));
                    tmp[t] = fmaxf(h, 0.f);
                }
                av.x = tmp[0]; av.y = tmp[1]; av.z = tmp[2]; av.w = tmp[3];
            } else { // BNRELU
                int k0 = kb + kq * 4;
                av = *(const float4*)&A[(size_t)(rowBase + row) * 256 + k0];
                av.x = fmaxf(fmaf(av.x, g_s2[k0],     g_t2[k0]),     0.f);
                av.y = fmaxf(fmaf(av.y, g_s2[k0 + 1], g_t2[k0 + 1]), 0.f);
                av.z = fmaxf(fmaf(av.z, g_s2[k0 + 2], g_t2[k0 + 2]), 0.f);
                av.w = fmaxf(fmaf(av.w, g_s2[k0 + 3], g_t2[k0 + 3]), 0.f);
            }
            As[kq * 4 + 0][row] = av.x;
            As[kq * 4 + 1][row] = av.y;
            As[kq * 4 + 2][row] = av.z;
            As[kq * 4 + 3][row] = av.w;

            int o = f >> 3;
            float4 bv = *(const float4*)&W[(size_t)(nOff + o) * 256 + kb + kq * 4];
            Bs[kq * 4 + 0][o] = bv.x;
            Bs[kq * 4 + 1][o] = bv.y;
            Bs[kq * 4 + 2][o] = bv.z;
            Bs[kq * 4 + 3][o] = bv.w;
        }
        __syncthreads();
#pragma unroll 8
        for (int k = 0; k < 32; k++) {
            float4 a0 = *(const float4*)&As[k][ty * 8];
            float4 a1 = *(const float4*)&As[k][ty * 8 + 4];
            float4 b0 = *(const float4*)&Bs[k][tx * 8];
            float4 b1 = *(const float4*)&Bs[k][tx * 8 + 4];
            ull bp0 = pack2(b0.x, b0.y), bp1 = pack2(b0.z, b0.w);
            ull bp2 = pack2(b1.x, b1.y), bp3 = pack2(b1.z, b1.w);
            float ar[8] = {a0.x, a0.y, a0.z, a0.w, a1.x, a1.y, a1.z, a1.w};
#pragma unroll
            for (int i = 0; i < 8; i++) {
                ull ad = dup2(ar[i]);
                ffma2(acc[i][0], ad, bp0);
                ffma2(acc[i][1], ad, bp1);
                ffma2(acc[i][2], ad, bp2);
                ffma2(acc[i][3], ad, bp3);
            }
        }
        __syncthreads();
    }

    float bs[8];
#pragma unroll
    for (int j = 0; j < 8; j++) bs[j] = bias[nOff + tx * 8 + j];
#pragma unroll
    for (int i = 0; i < 8; i++) {
        size_t off = (size_t)(rowBase + ty * 8 + i) * 256 + nOff + tx * 8;
        float2 p0 = unpk(acc[i][0]), p1 = unpk(acc[i][1]);
        float2 p2 = unpk(acc[i][2]), p3 = unpk(acc[i][3]);
        float4 o0 = {p0.x + bs[0], p0.y + bs[1], p1.x + bs[2], p1.y + bs[3]};
        float4 o1 = {p2.x + bs[4], p2.y + bs[5], p3.x + bs[6], p3.y + bs[7]};
        *(float4*)&Out[off]     = o0;
        *(float4*)&Out[off + 4] = o1;
    }
}

// ----------------------- K8: attention elementwise --------------------------
// One warp per row; lane l holds channels [4l..4l+3] and [128+4l..128+4l+3].
__global__ void __launch_bounds__(256) attn_kernel(const float* __restrict__ convw) {
    __shared__ float cw[1024];        // (8 groups, 4 out, 32 in)
    __shared__ float va[8][264];      // per-warp, 8 groups * 33 (padded)
    __shared__ float red[8][256];
    int tid = threadIdx.x, w = tid >> 5, l = tid & 31;
    for (int i = tid; i < 1024; i += 256) cw[i] = convw[i];
    __syncthreads();

    float cwr[32];                    // conv row for this lane's omega output
#pragma unroll
    for (int i = 0; i < 32; i++) cwr[i] = cw[(l >> 2) * 128 + (l & 3) * 32 + i];

    float sum0[4] = {0, 0, 0, 0}, sum1[4] = {0, 0, 0, 0};
    float sq0[4]  = {0, 0, 0, 0}, sq1[4]  = {0, 0, 0, 0};

    int base = blockIdx.x * 512 + w * 64;
    int g0 = (l >> 3), i0 = (l & 7) * 4;

    for (int it = 0; it < 64; it++) {
        int r = base + it;
        const float4* dm4 = (const float4*)(g_dm + (size_t)r * 256);
        const float4* db4 = (const float4*)(g_db + (size_t)r * 256);
        const float4* k4  = (const float4*)(g_k  + (size_t)r * 256);
        const float4* v4  = (const float4*)(g_v  + (size_t)r * 256);
        const float4* q4  = (const float4*)(g_q  + (size_t)(r >> 4) * 256);

        float4 dmv0 = dm4[l], dmv1 = dm4[32 + l];
        float4 dbv0 = db4[l], dbv1 = db4[32 + l];
        float4 kv0  = k4[l],  kv1  = k4[32 + l];
        float4 vv0  = v4[l],  vv1  = v4[32 + l];
        float4 qv0  = q4[l],  qv1  = q4[32 + l];

        float va0[4], va1[4];
        va0[0] = fmaf(dmv0.x, qv0.x - kv0.x, dbv0.x);
        va0[1] = fmaf(dmv0.y, qv0.y - kv0.y, dbv0.y);
        va0[2] = fmaf(dmv0.z, qv0.z - kv0.z, dbv0.z);
        va0[3] = fmaf(dmv0.w, qv0.w - kv0.w, dbv0.w);
        va1[0] = fmaf(dmv1.x, qv1.x - kv1.x, dbv1.x);
        va1[1] = fmaf(dmv1.y, qv1.y - kv1.y, dbv1.y);
        va1[2] = fmaf(dmv1.z, qv1.z - kv1.z, dbv1.z);
        va1[3] = fmaf(dmv1.w, qv1.w - kv1.w, dbv1.w);
#pragma unroll
        for (int t = 0; t < 4; t++) {
            va[w][g0 * 33 + i0 + t]       = va0[t];
            va[w][(4 + g0) * 33 + i0 + t] = va1[t];
        }
        __syncwarp();

        float acc = 0.f;
#pragma unroll
        for (int i = 0; i < 32; i++) acc = fmaf(va[w][(l >> 2) * 33 + i], cwr[i], acc);

        float mx = acc;
#pragma unroll
        for (int off = 16; off > 0; off >>= 1)
            mx = fmaxf(mx, __shfl_xor_sync(0xffffffffu, mx, off));
        float e = expf(acc - mx);
        float ssum = e;
#pragma unroll
        for (int off = 16; off > 0; off >>= 1)
            ssum += __shfl_xor_sync(0xffffffffu, ssum, off);
        float ome = e / ssum;

        float o0 = __shfl_sync(0xffffffffu, ome, l >> 1);
        float o1 = __shfl_sync(0xffffffffu, ome, 16 + (l >> 1));

        float4 we0 = {o0 * vv0.x, o0 * vv0.y, o0 * vv0.z, o0 * vv0.w};
        float4 we1 = {o1 * vv1.x, o1 * vv1.y, o1 * vv1.z, o1 * vv1.w};
        float4* we4 = (float4*)(g_we + (size_t)r * 256);
        we4[l]      = we0;
        we4[32 + l] = we1;

        sum0[0] += we0.x; sum0[1] += we0.y; sum0[2] += we0.z; sum0[3] += we0.w;
        sum1[0] += we1.x; sum1[1] += we1.y; sum1[2] += we1.z; sum1[3] += we1.w;
        sq0[0] += we0.x * we0.x; sq0[1] += we0.y * we0.y;
        sq0[2] += we0.z * we0.z; sq0[3] += we0.w * we0.w;
        sq1[0] += we1.x * we1.x; sq1[1] += we1.y * we1.y;
        sq1[2] += we1.z * we1.z; sq1[3] += we1.w * we1.w;
        __syncwarp();
    }

    // deterministic per-block channel reduction: sums, then sumsqs
#pragma unroll
    for (int t = 0; t < 4; t++) {
        red[w][4 * l + t]       = sum0[t];
        red[w][128 + 4 * l + t] = sum1[t];
    }
    __syncthreads();
    {
        float a = 0.f;
#pragma unroll
        for (int ww = 0; ww < 8; ww++) a += red[ww][tid];
        g_part2[blockIdx.x * 512 + tid] = a;
    }
    __syncthreads();
#pragma unroll
    for (int t = 0; t < 4; t++) {
        red[w][4 * l + t]       = sq0[t];
        red[w][128 + 4 * l + t] = sq1[t];
    }
    __syncthreads();
    {
        float a = 0.f;
#pragma unroll
        for (int ww = 0; ww < 8; ww++) a += red[ww][tid];
        g_part2[blockIdx.x * 512 + 256 + tid] = a;
    }
}

// --------------------------- K9: BN2 finalize -------------------------------
__global__ void finalize2_kernel(const float* __restrict__ bn_g,
                                 const float* __restrict__ bn_b) {
    int c = threadIdx.x;
    float s = 0.f, sq = 0.f;
    for (int b = 0; b < ATTN_BLOCKS; b++) {
        s  += g_part2[b * 512 + c];
        sq += g_part2[b * 512 + 256 + c];
    }
    float mean = s / (float)R_;
    float var = sq / (float)R_ - mean * mean;
    float sc = bn_g[c] * rsqrtf(var + EPSV);
    g_s2[c] = sc;
    g_t2[c] = bn_b[c] - mean * sc;
}

// ------------------------------- launch -------------------------------------
extern "C" void kernel_launch(void* const* d_in, const int* in_sizes, int n_in,
                              void* d_out, int out_size) {
    const float* pts   = (const float*)d_in[0];
    const float* pf    = (const float*)d_in[1];
    const float* nbr   = (const float*)d_in[2];
    const float* nf    = (const float*)d_in[3];
    const float* dm_w1 = (const float*)d_in[4];
    const float* dm_b1 = (const float*)d_in[5];
    const float* dm_w2 = (const float*)d_in[6];
    const float* dm_b2 = (const float*)d_in[7];
    const float* dm_g  = (const float*)d_in[8];
    const float* dm_be = (const float*)d_in[9];
    const float* db_w1 = (const float*)d_in[10];
    const float* db_b1 = (const float*)d_in[11];
    const float* db_w2 = (const float*)d_in[12];
    const float* db_b2 = (const float*)d_in[13];
    const float* db_g  = (const float*)d_in[14];
    const float* db_be = (const float*)d_in[15];
    const float* q_w   = (const float*)d_in[16];
    const float* q_b   = (const float*)d_in[17];
    const float* k_w   = (const float*)d_in[18];
    const float* k_b   = (const float*)d_in[19];
    const float* v_w   = (const float*)d_in[20];
    const float* v_b   = (const float*)d_in[21];
    const float* convw = (const float*)d_in[22];
    const float* bn_g  = (const float*)d_in[23];
    const float* bn_b  = (const float*)d_in[24];
    const float* lin_w = (const float*)d_in[25];
    const float* lin_b = (const float*)d_in[26];
    float* out = (float*)d_out;

    void *p_q, *p_dm, *p_db, *p_k, *p_v, *p_we;
    cudaGetSymbolAddress(&p_q,  g_q);
    cudaGetSymbolAddress(&p_dm, g_dm);
    cudaGetSymbolAddress(&p_db, g_db);
    cudaGetSymbolAddress(&p_k,  g_k);
    cudaGetSymbolAddress(&p_v,  g_v);
    cudaGetSymbolAddress(&p_we, g_we);

    diffstats_kernel<<<STAT_BLOCKS, 256>>>(pts, nbr);
    fold_kernel<<<1, 256>>>(dm_w1, dm_b1, dm_g, dm_be, db_w1, db_b1, db_g, db_be);

    dim3 gq(BNp / 128, 2);
    dim3 gr(R_ / 128, 2);
    gemm_kernel<AMODE_DIRECT><<<gq, 256>>>(pf, q_w, q_b, (float*)p_q, nullptr, nullptr, 0);
    gemm_kernel<AMODE_POS><<<gr, 256>>>(nullptr, dm_w2, dm_b2, (float*)p_dm, pts, nbr, 0);
    gemm_kernel<AMODE_POS><<<gr, 256>>>(nullptr, db_w2, db_b2, (float*)p_db, pts, nbr, 1);
    gemm_kernel<AMODE_DIRECT><<<gr, 256>>>(nf, k_w, k_b, (float*)p_k, nullptr, nullptr, 0);
    gemm_kernel<AMODE_DIRECT><<<gr, 256>>>(nf, v_w, v_b, (float*)p_v, nullptr, nullptr, 0);

    attn_kernel<<<ATTN_BLOCKS, 256>>>(convw);
    finalize2_kernel<<<1, 256>>>(bn_g, bn_b);

    gemm_kernel<AMODE_BNRELU><<<gr, 256>>>((const float*)p_we, lin_w, lin_b, out,
                                           nullptr, nullptr, 0);
}

// round 3
// speedup vs baseline: 2.7295x; 2.7295x over previous
#include <cuda_runtime.h>
#include <cstdint>

// ---------------------------------------------------------------------------
// GroupVectorAttention — mma.sync tf32 GEMMs (sm_80+ PTX, runs on sm_103
// tensor pipe) + analytic BN1 folding. tcgen05 is unavailable: harness ptxas
// targets sm_103 (no 'a'), which rejects all tcgen05/arch-specific features.
// ---------------------------------------------------------------------------

#define EPSV 1e-5f

static constexpr int Bb = 4, Nn = 4096, Mm = 16, Cd = 256;
static constexpr int R_ = Bb * Nn * Mm;       // 262144
static constexpr int BNp = Bb * Nn;           // 16384
static constexpr int STAT_BLOCKS = 256;
static constexpr int ATTN_BLOCKS = 512;

// smem float offsets (A stride-36 padded; B double-buffered)
static constexpr int SOFF_A    = 0;            // 128*36 = 4608
static constexpr int SOFF_B    = 4608;         // 2 * 128*36 = 9216
static constexpr int SOFF_BIAS = 13824;        // 256
static constexpr int SOFF_W1F  = 14080;        // 768
static constexpr int SOFF_B1F  = 14848;        // 256
static constexpr int SOFF_S2   = 15104;        // 256
static constexpr int SOFF_T2   = 15360;        // 256
static constexpr int SOFF_DIFF = 15616;        // 128*4
static constexpr int SMEM_FLOATS = 16128;      // 64512 bytes
static constexpr int DYN_SMEM = SMEM_FLOATS * 4;

// ------------------------- device scratch (static) -------------------------
__device__ float g_part1[STAT_BLOCKS * 12];
__device__ float g_w1f[2][Cd * 3];
__device__ float g_b1f[2][Cd];
__device__ float g_q[BNp * Cd];
__device__ float g_dm[(size_t)R_ * Cd];
__device__ float g_db[(size_t)R_ * Cd];
__device__ float g_k [(size_t)R_ * Cd];
__device__ float g_v [(size_t)R_ * Cd];
__device__ float g_we[(size_t)R_ * Cd];
__device__ float g_part2[ATTN_BLOCKS * 512];
__device__ float g_s2[Cd], g_t2[Cd];

// ----------------------------- PTX helpers ---------------------------------
__device__ __forceinline__ uint32_t smem_u32(const void* p) {
    uint32_t a;
    asm("{ .reg .u64 t; cvta.to.shared.u64 t, %1; cvt.u32.u64 %0, t; }"
        : "=r"(a) : "l"(p));
    return a;
}
__device__ __forceinline__ uint32_t cvt_tf32(float f) {
    uint32_t u; asm("cvt.rna.tf32.f32 %0, %1;" : "=r"(u) : "f"(f)); return u;
}
__device__ __forceinline__ void cp16(uint32_t dst, const void* src) {
    asm volatile("cp.async.cg.shared.global [%0], [%1], 16;"
                 :: "r"(dst), "l"(src) : "memory");
}
__device__ __forceinline__ void cp_commit() {
    asm volatile("cp.async.commit_group;" ::: "memory");
}
template <int N>
__device__ __forceinline__ void cp_wait() {
    asm volatile("cp.async.wait_group %0;" :: "n"(N) : "memory");
}
__device__ __forceinline__ void mma_tf32(float* c, const uint32_t* a, const uint32_t* b) {
    asm volatile("mma.sync.aligned.m16n8k8.row.col.f32.tf32.tf32.f32 "
                 "{%0,%1,%2,%3}, {%4,%5,%6,%7}, {%8,%9}, {%0,%1,%2,%3};"
                 : "+f"(c[0]), "+f"(c[1]), "+f"(c[2]), "+f"(c[3])
                 : "r"(a[0]), "r"(a[1]), "r"(a[2]), "r"(a[3]),
                   "r"(b[0]), "r"(b[1]));
}

// ------------------------------- K1: stats --------------------------------
__global__ void diffstats_kernel(const float* __restrict__ pts,
                                 const float* __restrict__ nbr) {
    float s[12];
#pragma unroll
    for (int i = 0; i < 12; i++) s[i] = 0.f;
    int tid = threadIdx.x;
    for (int r = blockIdx.x * blockDim.x + tid; r < R_; r += gridDim.x * blockDim.x) {
        int bn = r >> 4;
        float d[3];
#pragma unroll
        for (int j = 0; j < 3; j++) d[j] = pts[bn * 3 + j] - nbr[(size_t)r * 3 + j];
#pragma unroll
        for (int j = 0; j < 3; j++) s[j] += d[j];
#pragma unroll
        for (int j = 0; j < 3; j++)
#pragma unroll
            for (int k = 0; k < 3; k++) s[3 + j * 3 + k] += d[j] * d[k];
    }
    __shared__ float red[256];
    for (int comp = 0; comp < 12; comp++) {
        red[tid] = s[comp];
        __syncthreads();
        for (int off = 128; off > 0; off >>= 1) {
            if (tid < off) red[tid] += red[tid + off];
            __syncthreads();
        }
        if (tid == 0) g_part1[blockIdx.x * 12 + comp] = red[0];
        __syncthreads();
    }
}

// ------------------------------ K2: BN1 fold -------------------------------
__global__ void fold_kernel(const float* __restrict__ dm_w1, const float* __restrict__ dm_b1,
                            const float* __restrict__ dm_g,  const float* __restrict__ dm_be,
                            const float* __restrict__ db_w1, const float* __restrict__ db_b1,
                            const float* __restrict__ db_g,  const float* __restrict__ db_be) {
    __shared__ float st[12];
    __shared__ float mu[3], cov[9];
    int tid = threadIdx.x;
    if (tid < 12) {
        float a = 0.f;
        for (int b = 0; b < STAT_BLOCKS; b++) a += g_part1[b * 12 + tid];
        st[tid] = a / (float)R_;
    }
    __syncthreads();
    if (tid < 3) mu[tid] = st[tid];
    if (tid < 9) {
        int j = tid / 3, k = tid % 3;
        cov[tid] = st[3 + tid] - st[j] * st[k];
    }
    __syncthreads();
    int c = tid;
    for (int which = 0; which < 2; which++) {
        const float* w1 = which ? db_w1 : dm_w1;
        const float* b1 = which ? db_b1 : dm_b1;
        const float* gg = which ? db_g  : dm_g;
        const float* be = which ? db_be : dm_be;
        float w0 = w1[c * 3], w1v = w1[c * 3 + 1], w2v = w1[c * 3 + 2];
        float var = w0 * w0 * cov[0] + w1v * w1v * cov[4] + w2v * w2v * cov[8]
                  + 2.f * (w0 * w1v * cov[1] + w0 * w2v * cov[2] + w1v * w2v * cov[5]);
        float mdot = w0 * mu[0] + w1v * mu[1] + w2v * mu[2];
        float m = mdot + b1[c];
        float s = gg[c] * rsqrtf(var + EPSV);
        g_w1f[which][c * 3]     = w0 * s;
        g_w1f[which][c * 3 + 1] = w1v * s;
        g_w1f[which][c * 3 + 2] = w2v * s;
        g_b1f[which][c] = be[c] + s * (b1[c] - m);
    }
}

// ----------------------- GEMM: mma.sync tf32 (m16n8k8) ---------------------
// CTA tile: 128 rows x 128 cols (grid.y=2), K=256 in 8 chunks of 32.
// 8 warps, 2(row) x 4(col); warp tile 64x32; 4x4 m16n8 microtiles.
enum { AMODE_DIRECT = 0, AMODE_POS = 1, AMODE_BNRELU = 2 };

template <int AMODE>
__device__ __forceinline__ void load_a_regs(
    int tid, int rowBase, int kb,
    const float* __restrict__ A,
    const float* w1f_s, const float* b1f_s,
    const float* s2_s, const float* t2_s, const float* diff_s,
    uint4 aR[4]) {
#pragma unroll
    for (int i = 0; i < 4; i++) {
        int f = tid + i * 256, row = f >> 3, kq = f & 7;
        float4 v;
        if (AMODE == AMODE_POS) {
            float d0 = diff_s[row * 4], d1 = diff_s[row * 4 + 1], d2 = diff_s[row * 4 + 2];
            float t[4];
#pragma unroll
            for (int j = 0; j < 4; j++) {
                int k = kb + kq * 4 + j;
                float h = fmaf(d0, w1f_s[k * 3],
                          fmaf(d1, w1f_s[k * 3 + 1],
                          fmaf(d2, w1f_s[k * 3 + 2], b1f_s[k])));
                t[j] = fmaxf(h, 0.f);
            }
            v = make_float4(t[0], t[1], t[2], t[3]);
        } else {
            v = *(const float4*)&A[(size_t)(rowBase + row) * 256 + kb + kq * 4];
            if (AMODE == AMODE_BNRELU) {
                int k = kb + kq * 4;
                v.x = fmaxf(fmaf(v.x, s2_s[k],     t2_s[k]),     0.f);
                v.y = fmaxf(fmaf(v.y, s2_s[k + 1], t2_s[k + 1]), 0.f);
                v.z = fmaxf(fmaf(v.z, s2_s[k + 2], t2_s[k + 2]), 0.f);
                v.w = fmaxf(fmaf(v.w, s2_s[k + 3], t2_s[k + 3]), 0.f);
            }
        }
        aR[i].x = cvt_tf32(v.x); aR[i].y = cvt_tf32(v.y);
        aR[i].z = cvt_tf32(v.z); aR[i].w = cvt_tf32(v.w);
    }
}

template <int AMODE>
__global__ void __launch_bounds__(256, 2)
gemm_mma(const float* __restrict__ A, const float* __restrict__ W,
         const float* __restrict__ bias, float* __restrict__ Out,
         const float* __restrict__ pts, const float* __restrict__ nbr, int which) {
    extern __shared__ float sm[];
    float* A_s    = sm + SOFF_A;
    float* B_s    = sm + SOFF_B;
    float* bias_s = sm + SOFF_BIAS;
    float* w1f_s  = sm + SOFF_W1F;
    float* b1f_s  = sm + SOFF_B1F;
    float* s2_s   = sm + SOFF_S2;
    float* t2_s   = sm + SOFF_T2;
    float* diff_s = sm + SOFF_DIFF;

    int tid = threadIdx.x;
    int rowBase = blockIdx.x * 128;
    int nOff = blockIdx.y * 128;

    bias_s[tid] = bias[tid];
    if (AMODE == AMODE_POS) {
        const float* w1f = g_w1f[which];
        for (int i = tid; i < 768; i += 256) w1f_s[i] = w1f[i];
        b1f_s[tid] = g_b1f[which][tid];
        if (tid < 128) {
            int r = rowBase + tid, bn = r >> 4;
            diff_s[tid * 4 + 0] = pts[bn * 3 + 0] - nbr[(size_t)r * 3 + 0];
            diff_s[tid * 4 + 1] = pts[bn * 3 + 1] - nbr[(size_t)r * 3 + 1];
            diff_s[tid * 4 + 2] = pts[bn * 3 + 2] - nbr[(size_t)r * 3 + 2];
        }
    }
    if (AMODE == AMODE_BNRELU) {
        s2_s[tid] = g_s2[tid];
        t2_s[tid] = g_t2[tid];
    }
    __syncthreads();   // diff_s / w1f_s visible to A producers

    // B cp.async: thread covers row n = tid>>3 (+32..), kq = tid&7
    int bn_row = tid >> 3, bkq = tid & 7;
    uint32_t bsts_base = smem_u32(B_s) + (uint32_t)(bn_row * 36 + bkq * 4) * 4u;
    const float* bsrc_base = W + (size_t)(nOff + bn_row) * 256 + bkq * 4;

    auto cp_b = [&](int buf, int kb) {
#pragma unroll
        for (int i = 0; i < 4; i++) {
            cp16(bsts_base + (uint32_t)(buf * 4608 + i * 32 * 36) * 4u,
                 bsrc_base + (size_t)i * 32 * 256 + kb);
        }
        cp_commit();
    };
    auto sts_a = [&](const uint4* aR) {
#pragma unroll
        for (int i = 0; i < 4; i++) {
            int f = tid + i * 256, row = f >> 3, kq = f & 7;
            *(uint4*)&A_s[row * 36 + kq * 4] = aR[i];
        }
    };

    // prologue
    cp_b(0, 0);
    cp_b(1, 32);
    uint4 aR[4];
    load_a_regs<AMODE>(tid, rowBase, 0, A, w1f_s, b1f_s, s2_s, t2_s, diff_s, aR);
    sts_a(aR);
    cp_wait<1>();
    __syncthreads();

    int lane = tid & 31, w = tid >> 5;
    int wm = w & 1, wn = w >> 1;
    const uint32_t* Aw = (const uint32_t*)(A_s + (wm * 64 + (lane >> 2)) * 36 + (lane & 3));

    float acc[4][4][4];
#pragma unroll
    for (int mt = 0; mt < 4; mt++)
#pragma unroll
        for (int nt = 0; nt < 4; nt++)
#pragma unroll
            for (int r = 0; r < 4; r++) acc[mt][nt][r] = 0.f;

    for (int s = 0; s < 8; s++) {
        if (s < 7)
            load_a_regs<AMODE>(tid, rowBase, (s + 1) * 32, A,
                               w1f_s, b1f_s, s2_s, t2_s, diff_s, aR);
        const uint32_t* Bw = (const uint32_t*)
            (B_s + (s & 1) * 4608 + (wn * 32 + (lane >> 2)) * 36 + (lane & 3));
#pragma unroll
        for (int kt = 0; kt < 4; kt++) {
            uint32_t bf[4][2], af[4][4];
#pragma unroll
            for (int nt = 0; nt < 4; nt++) {
                bf[nt][0] = Bw[nt * 288 + kt * 8];
                bf[nt][1] = Bw[nt * 288 + kt * 8 + 4];
            }
#pragma unroll
            for (int mt = 0; mt < 4; mt++) {
                af[mt][0] = Aw[mt * 576 + kt * 8];
                af[mt][1] = Aw[mt * 576 + 288 + kt * 8];
                af[mt][2] = Aw[mt * 576 + kt * 8 + 4];
                af[mt][3] = Aw[mt * 576 + 288 + kt * 8 + 4];
            }
#pragma unroll
            for (int mt = 0; mt < 4; mt++)
#pragma unroll
                for (int nt = 0; nt < 4; nt++)
                    mma_tf32(acc[mt][nt], af[mt], bf[nt]);
        }
        __syncthreads();
        if (s < 6) cp_b(s & 1, (s + 2) * 32);
        if (s < 7) {
            sts_a(aR);
            cp_wait<1>();
            __syncthreads();
        }
    }

    // epilogue: direct float2 stores (+bias)
#pragma unroll
    for (int mt = 0; mt < 4; mt++) {
        int row0 = rowBase + wm * 64 + mt * 16 + (lane >> 2);
#pragma unroll
        for (int nt = 0; nt < 4; nt++) {
            int col = nOff + wn * 32 + nt * 8 + 2 * (lane & 3);
            float b0 = bias_s[col - nOff + (nOff ? 128 : 0)]; // bias_s holds cols [0,256)
            // bias_s is indexed by global col; recompute cleanly:
            b0 = bias_s[col & 255];
            float b1 = bias_s[(col + 1) & 255];
            float2 v0 = {acc[mt][nt][0] + b0, acc[mt][nt][1] + b1};
            float2 v1 = {acc[mt][nt][2] + b0, acc[mt][nt][3] + b1};
            *(float2*)&Out[(size_t)row0 * 256 + col] = v0;
            *(float2*)&Out[(size_t)(row0 + 8) * 256 + col] = v1;
        }
    }
}

// ----------------------- K8: attention elementwise --------------------------
__global__ void __launch_bounds__(256) attn_kernel(const float* __restrict__ convw) {
    __shared__ float cw[1024];
    __shared__ float va[8][264];
    __shared__ float red[8][256];
    int tid = threadIdx.x, w = tid >> 5, l = tid & 31;
    for (int i = tid; i < 1024; i += 256) cw[i] = convw[i];
    __syncthreads();

    float cwr[32];
#pragma unroll
    for (int i = 0; i < 32; i++) cwr[i] = cw[(l >> 2) * 128 + (l & 3) * 32 + i];

    float sum0[4] = {0, 0, 0, 0}, sum1[4] = {0, 0, 0, 0};
    float sq0[4]  = {0, 0, 0, 0}, sq1[4]  = {0, 0, 0, 0};

    int base = blockIdx.x * 512 + w * 64;
    int g0 = (l >> 3), i0 = (l & 7) * 4;

    for (int it = 0; it < 64; it++) {
        int r = base + it;
        const float4* dm4 = (const float4*)(g_dm + (size_t)r * 256);
        const float4* db4 = (const float4*)(g_db + (size_t)r * 256);
        const float4* k4  = (const float4*)(g_k  + (size_t)r * 256);
        const float4* v4  = (const float4*)(g_v  + (size_t)r * 256);
        const float4* q4  = (const float4*)(g_q  + (size_t)(r >> 4) * 256);

        float4 dmv0 = dm4[l], dmv1 = dm4[32 + l];
        float4 dbv0 = db4[l], dbv1 = db4[32 + l];
        float4 kv0  = k4[l],  kv1  = k4[32 + l];
        float4 vv0  = v4[l],  vv1  = v4[32 + l];
        float4 qv0  = q4[l],  qv1  = q4[32 + l];

        float va0[4], va1[4];
        va0[0] = fmaf(dmv0.x, qv0.x - kv0.x, dbv0.x);
        va0[1] = fmaf(dmv0.y, qv0.y - kv0.y, dbv0.y);
        va0[2] = fmaf(dmv0.z, qv0.z - kv0.z, dbv0.z);
        va0[3] = fmaf(dmv0.w, qv0.w - kv0.w, dbv0.w);
        va1[0] = fmaf(dmv1.x, qv1.x - kv1.x, dbv1.x);
        va1[1] = fmaf(dmv1.y, qv1.y - kv1.y, dbv1.y);
        va1[2] = fmaf(dmv1.z, qv1.z - kv1.z, dbv1.z);
        va1[3] = fmaf(dmv1.w, qv1.w - kv1.w, dbv1.w);
#pragma unroll
        for (int t = 0; t < 4; t++) {
            va[w][g0 * 33 + i0 + t]       = va0[t];
            va[w][(4 + g0) * 33 + i0 + t] = va1[t];
        }
        __syncwarp();

        float acc = 0.f;
#pragma unroll
        for (int i = 0; i < 32; i++) acc = fmaf(va[w][(l >> 2) * 33 + i], cwr[i], acc);

        float mx = acc;
#pragma unroll
        for (int off = 16; off > 0; off >>= 1)
            mx = fmaxf(mx, __shfl_xor_sync(0xffffffffu, mx, off));
        float e = expf(acc - mx);
        float ssum = e;
#pragma unroll
        for (int off = 16; off > 0; off >>= 1)
            ssum += __shfl_xor_sync(0xffffffffu, ssum, off);
        float ome = e / ssum;

        float o0 = __shfl_sync(0xffffffffu, ome, l >> 1);
        float o1 = __shfl_sync(0xffffffffu, ome, 16 + (l >> 1));

        float4 we0 = {o0 * vv0.x, o0 * vv0.y, o0 * vv0.z, o0 * vv0.w};
        float4 we1 = {o1 * vv1.x, o1 * vv1.y, o1 * vv1.z, o1 * vv1.w};
        float4* we4 = (float4*)(g_we + (size_t)r * 256);
        we4[l]      = we0;
        we4[32 + l] = we1;

        sum0[0] += we0.x; sum0[1] += we0.y; sum0[2] += we0.z; sum0[3] += we0.w;
        sum1[0] += we1.x; sum1[1] += we1.y; sum1[2] += we1.z; sum1[3] += we1.w;
        sq0[0] += we0.x * we0.x; sq0[1] += we0.y * we0.y;
        sq0[2] += we0.z * we0.z; sq0[3] += we0.w * we0.w;
        sq1[0] += we1.x * we1.x; sq1[1] += we1.y * we1.y;
        sq1[2] += we1.z * we1.z; sq1[3] += we1.w * we1.w;
        __syncwarp();
    }

#pragma unroll
    for (int t = 0; t < 4; t++) {
        red[w][4 * l + t]       = sum0[t];
        red[w][128 + 4 * l + t] = sum1[t];
    }
    __syncthreads();
    {
        float a = 0.f;
#pragma unroll
        for (int ww = 0; ww < 8; ww++) a += red[ww][tid];
        g_part2[blockIdx.x * 512 + tid] = a;
    }
    __syncthreads();
#pragma unroll
    for (int t = 0; t < 4; t++) {
        red[w][4 * l + t]       = sq0[t];
        red[w][128 + 4 * l + t] = sq1[t];
    }
    __syncthreads();
    {
        float a = 0.f;
#pragma unroll
        for (int ww = 0; ww < 8; ww++) a += red[ww][tid];
        g_part2[blockIdx.x * 512 + 256 + tid] = a;
    }
}

// --------------------------- K9: BN2 finalize -------------------------------
__global__ void finalize2_kernel(const float* __restrict__ bn_g,
                                 const float* __restrict__ bn_b) {
    int c = threadIdx.x;
    float s = 0.f, sq = 0.f;
    for (int b = 0; b < ATTN_BLOCKS; b++) {
        s  += g_part2[b * 512 + c];
        sq += g_part2[b * 512 + 256 + c];
    }
    float mean = s / (float)R_;
    float var = sq / (float)R_ - mean * mean;
    float sc = bn_g[c] * rsqrtf(var + EPSV);
    g_s2[c] = sc;
    g_t2[c] = bn_b[c] - mean * sc;
}

// ------------------------------- launch -------------------------------------
extern "C" void kernel_launch(void* const* d_in, const int* in_sizes, int n_in,
                              void* d_out, int out_size) {
    const float* pts   = (const float*)d_in[0];
    const float* pf    = (const float*)d_in[1];
    const float* nbr   = (const float*)d_in[2];
    const float* nf    = (const float*)d_in[3];
    const float* dm_w1 = (const float*)d_in[4];
    const float* dm_b1 = (const float*)d_in[5];
    const float* dm_w2 = (const float*)d_in[6];
    const float* dm_b2 = (const float*)d_in[7];
    const float* dm_g  = (const float*)d_in[8];
    const float* dm_be = (const float*)d_in[9];
    const float* db_w1 = (const float*)d_in[10];
    const float* db_b1 = (const float*)d_in[11];
    const float* db_w2 = (const float*)d_in[12];
    const float* db_b2 = (const float*)d_in[13];
    const float* db_g  = (const float*)d_in[14];
    const float* db_be = (const float*)d_in[15];
    const float* q_w   = (const float*)d_in[16];
    const float* q_b   = (const float*)d_in[17];
    const float* k_w   = (const float*)d_in[18];
    const float* k_b   = (const float*)d_in[19];
    const float* v_w   = (const float*)d_in[20];
    const float* v_b   = (const float*)d_in[21];
    const float* convw = (const float*)d_in[22];
    const float* bn_g  = (const float*)d_in[23];
    const float* bn_b  = (const float*)d_in[24];
    const float* lin_w = (const float*)d_in[25];
    const float* lin_b = (const float*)d_in[26];
    float* out = (float*)d_out;

    void *p_q, *p_dm, *p_db, *p_k, *p_v, *p_we;
    cudaGetSymbolAddress(&p_q,  g_q);
    cudaGetSymbolAddress(&p_dm, g_dm);
    cudaGetSymbolAddress(&p_db, g_db);
    cudaGetSymbolAddress(&p_k,  g_k);
    cudaGetSymbolAddress(&p_v,  g_v);
    cudaGetSymbolAddress(&p_we, g_we);

    cudaFuncSetAttribute(gemm_mma<AMODE_DIRECT>,
                         cudaFuncAttributeMaxDynamicSharedMemorySize, DYN_SMEM);
    cudaFuncSetAttribute(gemm_mma<AMODE_POS>,
                         cudaFuncAttributeMaxDynamicSharedMemorySize, DYN_SMEM);
    cudaFuncSetAttribute(gemm_mma<AMODE_BNRELU>,
                         cudaFuncAttributeMaxDynamicSharedMemorySize, DYN_SMEM);

    diffstats_kernel<<<STAT_BLOCKS, 256>>>(pts, nbr);
    fold_kernel<<<1, 256>>>(dm_w1, dm_b1, dm_g, dm_be, db_w1, db_b1, db_g, db_be);

    dim3 gq(BNp / 128, 2);
    dim3 gr(R_ / 128, 2);
    gemm_mma<AMODE_DIRECT><<<gq, 256, DYN_SMEM>>>(
        pf, q_w, q_b, (float*)p_q, nullptr, nullptr, 0);
    gemm_mma<AMODE_POS><<<gr, 256, DYN_SMEM>>>(
        nullptr, dm_w2, dm_b2, (float*)p_dm, pts, nbr, 0);
    gemm_mma<AMODE_POS><<<gr, 256, DYN_SMEM>>>(
        nullptr, db_w2, db_b2, (float*)p_db, pts, nbr, 1);
    gemm_mma<AMODE_DIRECT><<<gr, 256, DYN_SMEM>>>(
        nf, k_w, k_b, (float*)p_k, nullptr, nullptr, 0);
    gemm_mma<AMODE_DIRECT><<<gr, 256, DYN_SMEM>>>(
        nf, v_w, v_b, (float*)p_v, nullptr, nullptr, 0);

    attn_kernel<<<ATTN_BLOCKS, 256>>>(convw);
    finalize2_kernel<<<1, 256>>>(bn_g, bn_b);

    gemm_mma<AMODE_BNRELU><<<gr, 256, DYN_SMEM>>>(
        (const float*)p_we, lin_w, lin_b, out, nullptr, nullptr, 0);
}